// round 6
// baseline (speedup 1.0000x reference)
#include <cuda_runtime.h>
#include <cuda_bf16.h>

#define BATCH 16
#define NN    1024
#define DD    64
#define EPSF      0.1f
#define INV_EPS   10.0f
#define LOG_MU   (-6.9314616f)   // log(1/1024 + 1e-8)
#define THRESH    0.1f
#define MAX_ITER  100
#define GB        128            // persistent grid: 128 blocks, all co-resident
#define TB        1024
#define RCH       16             // rows per chunk
#define NCHUNK    8              // 128 rows / 16

// ---------------- device scratch (static: no allocations allowed) ----------------
__device__ __nv_bfloat16 g_Kh[BATCH * NN * NN];  // 32 MB: K = exp(-C/eps), bf16
__device__ float g_xs[BATCH * NN * DD];
__device__ float g_ys[BATCH * NN * DD];
__device__ float g_x2[BATCH * NN];
__device__ float g_y2[BATCH * NN];
__device__ float g_b [BATCH * NN];        // exp(v/eps) — only cross-block vector
__device__ float g_s [BATCH * NN];        // col-sum accumulator s_j = sum_i K_ij a_i
__device__ float g_errA[MAX_ITER * BATCH];
__device__ double   g_cost;
__device__ unsigned g_bar_cnt;
__device__ unsigned g_bar_gen;

// ---------------- software grid barrier (all GB blocks co-resident) ----------------
__device__ __forceinline__ void grid_barrier() {
    __threadfence();
    __syncthreads();
    if (threadIdx.x == 0) {
        unsigned gen = *((volatile unsigned*)&g_bar_gen);
        if (atomicAdd(&g_bar_cnt, 1u) == GB - 1u) {
            g_bar_cnt = 0u;
            __threadfence();
            *((volatile unsigned*)&g_bar_gen) = gen + 1u;
        } else {
            while (*((volatile unsigned*)&g_bar_gen) == gen) { __nanosleep(64); }
        }
    }
    __syncthreads();
}

__device__ __forceinline__ float to_tf32(float x) {
    asm("cvt.rna.tf32.f32 %0, %0;" : "+f"(x));
    return x;
}

// dot of 8 bf16 (one uint4) with 8 floats (two float4)
__device__ __forceinline__ float dot8(uint4 q, float4 b0, float4 b1) {
    float2 p0 = __bfloat1622float2(*(const __nv_bfloat162*)&q.x);
    float2 p1 = __bfloat1622float2(*(const __nv_bfloat162*)&q.y);
    float2 p2 = __bfloat1622float2(*(const __nv_bfloat162*)&q.z);
    float2 p3 = __bfloat1622float2(*(const __nv_bfloat162*)&q.w);
    return p0.x*b0.x + p0.y*b0.y + p1.x*b0.z + p1.y*b0.w
         + p2.x*b1.x + p2.y*b1.y + p3.x*b1.z + p3.y*b1.w;
}

// sum of k*b*ln(k) over 8 bf16 k's
__device__ __forceinline__ float dot8log(uint4 q, float4 b0, float4 b1) {
    float2 p0 = __bfloat1622float2(*(const __nv_bfloat162*)&q.x);
    float2 p1 = __bfloat1622float2(*(const __nv_bfloat162*)&q.y);
    float2 p2 = __bfloat1622float2(*(const __nv_bfloat162*)&q.z);
    float2 p3 = __bfloat1622float2(*(const __nv_bfloat162*)&q.w);
    return p0.x*b0.x*__logf(p0.x) + p0.y*b0.y*__logf(p0.y)
         + p1.x*b0.z*__logf(p1.x) + p1.y*b0.w*__logf(p1.y)
         + p2.x*b1.x*__logf(p2.x) + p2.y*b1.y*__logf(p2.y)
         + p3.x*b1.z*__logf(p3.x) + p3.y*b1.w*__logf(p3.y);
}

// ---------------- softmax over last dim (D=64) + fused per-launch init ----------------
__global__ void softmax_kernel(const float* __restrict__ x, const float* __restrict__ y) {
    int gidx = blockIdx.x * blockDim.x + threadIdx.x;
    if (gidx < BATCH * NN) { g_b[gidx] = 1.f; g_s[gidx] = 0.f; }
    if (gidx < MAX_ITER * BATCH) g_errA[gidx] = 0.f;
    if (gidx == 0) { g_cost = 0.0; g_bar_cnt = 0u; g_bar_gen = 0u; }

    int gwarp = gidx >> 5;
    int lane  = threadIdx.x & 31;
    const float* src; float* dst; float* nrm; int row;
    if (gwarp < BATCH * NN) { src = x; dst = g_xs; nrm = g_x2; row = gwarp; }
    else                    { src = y; dst = g_ys; nrm = g_y2; row = gwarp - BATCH * NN; }
    const float* r = src + row * DD;
    float e0 = r[lane], e1 = r[lane + 32];
    float m = fmaxf(e0, e1);
    #pragma unroll
    for (int o = 16; o; o >>= 1) m = fmaxf(m, __shfl_xor_sync(0xFFFFFFFFu, m, o));
    float s0 = __expf(e0 - m), s1 = __expf(e1 - m);
    float s = s0 + s1;
    #pragma unroll
    for (int o = 16; o; o >>= 1) s += __shfl_xor_sync(0xFFFFFFFFu, s, o);
    float inv = 1.0f / s;
    float p0 = s0 * inv, p1 = s1 * inv;
    float* d = dst + row * DD;
    d[lane] = p0; d[lane + 32] = p1;
    float q = p0 * p0 + p1 * p1;
    #pragma unroll
    for (int o = 16; o; o >>= 1) q += __shfl_xor_sync(0xFFFFFFFFu, q, o);
    if (lane == 0) nrm[row] = q;
}

// ---------------- K = exp((2 x.y - |x|^2 - |y|^2)/eps) via tf32 MMA, bf16 store ----------------
#define XS_STRIDE 68
__global__ void __launch_bounds__(256) buildK_mma() {
    __shared__ float xs[64 * XS_STRIDE];
    __shared__ float ys[64 * XS_STRIDE];
    __shared__ float x2s[64], y2s[64];

    int bx = blockIdx.x;
    int batch = bx >> 8;
    int tile  = bx & 255;
    int i0 = (tile >> 4) * 64, j0 = (tile & 15) * 64;
    int t = threadIdx.x;

    const float4* xsrc = (const float4*)(g_xs + (size_t)(batch * NN + i0) * DD);
    const float4* ysrc = (const float4*)(g_ys + (size_t)(batch * NN + j0) * DD);
    #pragma unroll
    for (int k = 0; k < 4; k++) {
        int lin = k * 256 + t;
        int row = lin >> 4, c = (lin & 15) * 4;
        float4 vx = xsrc[lin];
        float4 vy = ysrc[lin];
        vx.x = to_tf32(vx.x); vx.y = to_tf32(vx.y); vx.z = to_tf32(vx.z); vx.w = to_tf32(vx.w);
        vy.x = to_tf32(vy.x); vy.y = to_tf32(vy.y); vy.z = to_tf32(vy.z); vy.w = to_tf32(vy.w);
        *((float4*)(xs + row * XS_STRIDE + c)) = vx;
        *((float4*)(ys + row * XS_STRIDE + c)) = vy;
    }
    if (t < 64)            x2s[t]      = g_x2[batch * NN + i0 + t];
    else if (t < 128)      y2s[t - 64] = g_y2[batch * NN + j0 + (t - 64)];
    __syncthreads();

    int w = t >> 5, lane = t & 31;
    int mo = (w >> 1) * 16;
    int no = (w & 1) * 32;
    int gr = lane >> 2, gc = lane & 3;

    float acc[4][4];
    #pragma unroll
    for (int nt = 0; nt < 4; nt++)
        #pragma unroll
        for (int q = 0; q < 4; q++) acc[nt][q] = 0.f;

    #pragma unroll
    for (int k0 = 0; k0 < 64; k0 += 8) {
        unsigned a0, a1, a2, a3;
        {
            const float* base = xs + (mo + gr) * XS_STRIDE + k0 + gc;
            a0 = __float_as_uint(base[0]);
            a1 = __float_as_uint(base[8 * XS_STRIDE]);
            a2 = __float_as_uint(base[4]);
            a3 = __float_as_uint(base[8 * XS_STRIDE + 4]);
        }
        #pragma unroll
        for (int nt = 0; nt < 4; nt++) {
            const float* bb = ys + (no + nt * 8 + gr) * XS_STRIDE + k0 + gc;
            unsigned b0 = __float_as_uint(bb[0]);
            unsigned b1 = __float_as_uint(bb[4]);
            asm volatile(
                "mma.sync.aligned.m16n8k8.row.col.f32.tf32.tf32.f32 "
                "{%0,%1,%2,%3}, {%4,%5,%6,%7}, {%8,%9}, {%0,%1,%2,%3};"
                : "+f"(acc[nt][0]), "+f"(acc[nt][1]), "+f"(acc[nt][2]), "+f"(acc[nt][3])
                : "r"(a0), "r"(a1), "r"(a2), "r"(a3), "r"(b0), "r"(b1));
        }
    }

    __nv_bfloat16* Kb = g_Kh + (size_t)batch * NN * NN;
    float xi0 = x2s[mo + gr], xi1 = x2s[mo + gr + 8];
    int r0 = i0 + mo + gr, r1 = r0 + 8;
    #pragma unroll
    for (int nt = 0; nt < 4; nt++) {
        int jc = j0 + no + nt * 8 + gc * 2;
        float yj0 = y2s[no + nt * 8 + gc * 2];
        float yj1 = y2s[no + nt * 8 + gc * 2 + 1];
        float k00 = __expf((2.0f * acc[nt][0] - xi0 - yj0) * INV_EPS);
        float k01 = __expf((2.0f * acc[nt][1] - xi0 - yj1) * INV_EPS);
        float k10 = __expf((2.0f * acc[nt][2] - xi1 - yj0) * INV_EPS);
        float k11 = __expf((2.0f * acc[nt][3] - xi1 - yj1) * INV_EPS);
        *(__nv_bfloat162*)(Kb + (size_t)r0 * NN + jc) = __floats2bfloat162_rn(k00, k01);
        *(__nv_bfloat162*)(Kb + (size_t)r1 * NN + jc) = __floats2bfloat162_rn(k10, k11);
    }
}

// ---------------- persistent Sinkhorn: ONE K-sweep per iteration ----------------
// Block bk: batch = bk>>3, seg = bk&7; owns rows [seg*128,+128) (u,a in smem)
// and cols [seg*128,+128) (v in smem, b via global).
__global__ void __launch_bounds__(TB, 1) sinkhorn_persistent(float* __restrict__ out) {
    int bk  = blockIdx.x;
    int tid = threadIdx.x;
    int batch = bk >> 3;
    int seg   = bk & 7;

    __shared__ float4 bfull4[256];          // current b (1024 floats)
    __shared__ uint4  Ks4[RCH * 128];       // 16 rows x 1024 bf16 = 32 KB chunk
    __shared__ float  psumA[32];
    __shared__ float  u_s[128], a_s[128], v_s[128], derr_s[128];
    __shared__ int    s_done;
    const float* bfull = (const float*)bfull4;
    const __nv_bfloat16* Ksh = (const __nv_bfloat16*)Ks4;

    if (tid < 128) { u_s[tid] = 0.f; a_s[tid] = 1.f; v_s[tid] = 0.f; }

    int row = tid >> 6;          // 0..15 (row within chunk)
    int q   = tid & 63;          // uint4 index within row (q and q+64)
    const uint4* Kg = (const uint4*)(g_Kh + (size_t)(batch * NN + seg * 128) * NN);

    int it = 0;
    for (; it < MAX_ITER; ++it) {
        if (tid < 256) bfull4[tid] = ((const float4*)(g_b + batch * NN))[tid];
        float s_acc = 0.f;       // col accumulator: thread tid owns col tid
        // prefetch chunk 0
        uint4 pf0, pf1;
        { const uint4* src = Kg + (size_t)row * 128; pf0 = src[q]; pf1 = src[q + 64]; }

        for (int c = 0; c < NCHUNK; ++c) {
            __syncthreads();     // Ks free, bfull ready (c==0)
            Ks4[row * 128 + q]      = pf0;
            Ks4[row * 128 + q + 64] = pf1;
            // phase A: row dot with b
            float p = dot8(pf0, bfull4[2 * q],        bfull4[2 * q + 1])
                    + dot8(pf1, bfull4[2 * (q + 64)], bfull4[2 * (q + 64) + 1]);
            #pragma unroll
            for (int o = 16; o; o >>= 1) p += __shfl_xor_sync(0xFFFFFFFFu, p, o);
            if ((tid & 31) == 0) psumA[tid >> 5] = p;
            __syncthreads();     // psumA ready AND Ks fully written
            if (tid < 16) {
                int lr = c * RCH + tid;
                float rs = psumA[2 * tid] + psumA[2 * tid + 1];
                float uo = u_s[lr], a = a_s[lr];
                float lse = logf(fmaf(a, rs, 1e-6f));
                float un  = EPSF * (LOG_MU - lse) + uo;
                u_s[lr] = un;
                a_s[lr] = expf(un * INV_EPS);
                derr_s[lr] = fabsf(un - uo);
            }
            if (c + 1 < NCHUNK) {
                const uint4* src = Kg + (size_t)((c + 1) * RCH + row) * 128;
                pf0 = src[q]; pf1 = src[q + 64];
            }
            __syncthreads();     // a_s ready
            // phase B: accumulate s_j += a_new_i * K_ij from smem chunk
            #pragma unroll
            for (int i = 0; i < RCH; i++)
                s_acc += a_s[c * RCH + i] * __bfloat162float(Ksh[i * NN + tid]);
        }
        atomicAdd(&g_s[batch * NN + tid], s_acc);   // REDG, partials from 8 blocks
        __syncthreads();
        if (tid == 0) {
            float d = 0.f;
            #pragma unroll
            for (int k = 0; k < 128; k++) d += derr_s[k];
            atomicAdd(&g_errA[it * BATCH + batch], d);
        }
        grid_barrier();          // s complete, err posted, everywhere

        // v-update for owned cols + global convergence decision
        if (tid < 128) {
            int j  = seg * 128 + tid;
            int gj = batch * NN + j;
            float s  = *((volatile float*)&g_s[gj]);
            float bo = bfull[j];
            float vo = v_s[tid];
            float vn = EPSF * (LOG_MU - logf(fmaf(bo, s, 1e-6f))) + vo;
            v_s[tid] = vn;
            g_b[gj]  = expf(vn * INV_EPS);
            g_s[gj]  = 0.f;      // reset for next iteration
        }
        if (tid == 0) {
            float e = 0.f;
            #pragma unroll
            for (int bb = 0; bb < BATCH; bb++) e += *((volatile float*)&g_errA[it * BATCH + bb]);
            s_done = (e * (1.0f / BATCH) < THRESH) ? 1 : 0;
        }
        grid_barrier();          // new b + s resets visible; s_done set (syncthreads inside)
        if (s_done) break;
    }

    // ======== cost phase: -eps * sum_ij a_i b_j K_ij ln K_ij (one more K sweep) ========
    if (tid < 256) bfull4[tid] = ((const float4*)(g_b + batch * NN))[tid];
    __syncthreads();
    float cacc = 0.f;
    #pragma unroll
    for (int c = 0; c < NCHUNK; ++c) {
        const uint4* src = Kg + (size_t)(c * RCH + row) * 128;
        uint4 k0 = src[q], k1 = src[q + 64];
        float p = dot8log(k0, bfull4[2 * q],        bfull4[2 * q + 1])
                + dot8log(k1, bfull4[2 * (q + 64)], bfull4[2 * (q + 64) + 1]);
        cacc += a_s[c * RCH + row] * p;
    }
    #pragma unroll
    for (int o = 16; o; o >>= 1) cacc += __shfl_xor_sync(0xFFFFFFFFu, cacc, o);
    if ((tid & 31) == 0) psumA[tid >> 5] = cacc;
    __syncthreads();
    if (tid == 0) {
        float t = 0.f;
        #pragma unroll
        for (int k = 0; k < 32; k++) t += psumA[k];
        atomicAdd(&g_cost, (double)(-EPSF * t));
    }
    grid_barrier();
    if (bk == 0 && tid == 0) out[0] = (float)(*((volatile double*)&g_cost) * (1.0 / (double)BATCH));
}

// ---------------- launch ----------------
extern "C" void kernel_launch(void* const* d_in, const int* in_sizes, int n_in,
                              void* d_out, int out_size) {
    const float* x = (const float*)d_in[0];
    const float* y = (const float*)d_in[1];
    float* out = (float*)d_out;
    (void)in_sizes; (void)n_in; (void)out_size;

    softmax_kernel<<<4096, 256>>>(x, y);   // softmax + fused init
    buildK_mma<<<4096, 256>>>();           // tf32 HMMA, bf16 K store
    sinkhorn_persistent<<<GB, TB>>>(out);  // fused one-sweep Sinkhorn + cost
}